// round 6
// baseline (speedup 1.0000x reference)
#include <cuda_runtime.h>
#include <cstdint>

#define IMG_H 1536
#define IMG_W 1536
#define NB    4
#define TOW   28          // output tile width
#define TOH   12          // output tile height
#define NTX   55          // ceil(1536/28)
#define NTY   128         // 1536/12

typedef unsigned long long ull;

// ---------------- f32x2 packed helpers (sm_103a) ----------------
__device__ __forceinline__ ull pk2(float lo, float hi) {
    ull r;
    asm("mov.b64 %0, {%1, %2};" : "=l"(r) : "f"(lo), "f"(hi));
    return r;
}
__device__ __forceinline__ void ffma2(ull& d, ull a, ull b) {
    asm("fma.rn.f32x2 %0, %1, %2, %0;" : "+l"(d) : "l"(a), "l"(b));
}
__device__ __forceinline__ void unpk2(ull v, float& lo, float& hi) {
    asm("mov.b64 {%0, %1}, %2;" : "=f"(lo), "=f"(hi) : "l"(v));
}

// Conv inner block, co-pair packed accumulators.
// acc[p][q]: p = 0 (left col) / 1 (right col), q = co-pair (co 2q, 2q+1).
// Weights in smem, plain layout: sw[(cin*9+t)*16 + co]  (co contiguous).
// One LDS.128 -> 4 weights -> 8 FFMA2.
template<int CIN, int ISTR, int IPLANE>
__device__ __forceinline__ void conv_block(const float* __restrict__ sin,
                                           const float* __restrict__ sw,
                                           int col, int row, ull acc[2][8]) {
#pragma unroll 1
    for (int cin = 0; cin < CIN; ++cin) {
        const float* base = sin + cin * IPLANE + row * ISTR + col;
        ull dup[3][4];
#pragma unroll
        for (int dy = 0; dy < 3; ++dy) {
            const float* p = base + dy * ISTR;
            float2 a = *(const float2*)p;         // cols col, col+1
            float2 b = *(const float2*)(p + 2);   // cols col+2, col+3
            dup[dy][0] = pk2(a.x, a.x);
            dup[dy][1] = pk2(a.y, a.y);
            dup[dy][2] = pk2(b.x, b.x);
            dup[dy][3] = pk2(b.y, b.y);
        }
        const ulonglong2* w = (const ulonglong2*)sw + cin * 36;
#pragma unroll
        for (int t = 0; t < 9; ++t) {
            const int dy = t / 3, kx = t % 3;
#pragma unroll
            for (int j = 0; j < 4; ++j) {
                ulonglong2 wv = w[t * 4 + j];     // co 4j..4j+3
                ffma2(acc[0][2 * j],     dup[dy][kx],     wv.x);
                ffma2(acc[1][2 * j],     dup[dy][kx + 1], wv.x);
                ffma2(acc[0][2 * j + 1], dup[dy][kx],     wv.y);
                ffma2(acc[1][2 * j + 1], dup[dy][kx + 1], wv.y);
            }
        }
    }
}

// Transpose (co-pair, 2 cols) -> (col-pair per co plane), mask, store to smem.
__device__ __forceinline__ void mstore(float* p0, float* p1, ull aL, ull aR, ull mask) {
    float l0, l1, r0, r1;
    unpk2(aL, l0, l1);
    unpk2(aR, r0, r1);
    ull v0 = pk2(l0, r0);
    ull v1 = pk2(l1, r1);
    asm("mul.rn.f32x2 %0, %0, %1;" : "+l"(v0) : "l"(mask));
    asm("mul.rn.f32x2 %0, %0, %1;" : "+l"(v1) : "l"(mask));
    *(ull*)p0 = v0;
    *(ull*)p1 = v1;
}

// smem layout (floats):
//  s_h1 : 16 ch * 16 rows * 34 stride = 8704   (conv1 out, halo 2, 32 cols used)
//  s_h2 : 16 ch * 14 rows * 32 stride = 7168   (conv2 out, halo 1, 30 cols used)
//  s_in : 3 ch * 18 rows * 36 stride  = 1944   (input, halo 3, 34 cols used)
//  s_w1 : 432   s_w2 : 2304   s_w3 : 2304      (plain, co innermost)
// total = 22856 floats = 91424 bytes -> 2 CTAs/SM
#define SMEM_BYTES 91424

__global__ __launch_bounds__(256, 2)
void net_fused_kernel(const float* __restrict__ x,
                      const float* __restrict__ w1,
                      const float* __restrict__ w2,
                      const float* __restrict__ w3,
                      float* __restrict__ out) {
    extern __shared__ float sm[];
    float* s_h1 = sm;                 // 8704
    float* s_h2 = s_h1 + 8704;        // 7168
    float* s_in = s_h2 + 7168;        // 1944
    float* s_w1 = s_in + 1944;        // 432
    float* s_w2 = s_w1 + 432;         // 2304
    float* s_w3 = s_w2 + 2304;        // 2304

    const int tid = threadIdx.x;
    const int tx = tid & 15;          // col pair 2*tx
    const int ty = tid >> 4;          // row
    const int ox = blockIdx.x * TOW;
    const int oy = blockIdx.y * TOH;
    const int bz = blockIdx.z;

    // ---- Stage A: input halo tile (3 x 18 x 34, zero-padded) + weights ----
    {
        const float* xb = x + (size_t)bz * 3 * IMG_H * IMG_W;
        for (int i = tid; i < 3 * 18 * 34; i += 256) {
            int cin = i / 612;
            int rem = i - cin * 612;
            int rr  = rem / 34;
            int cc  = rem - rr * 34;
            int gy = oy - 3 + rr;
            int gx = ox - 3 + cc;
            float v = 0.0f;
            if ((unsigned)gy < IMG_H && (unsigned)gx < IMG_W)
                v = xb[(size_t)cin * IMG_H * IMG_W + (size_t)gy * IMG_W + gx];
            s_in[cin * 648 + rr * 36 + cc] = v;
        }
        // transpose weights: s_w[(cin*9+t)*16 + co] = w[co][cin*9+t]
        for (int i = tid; i < 432; i += 256)
            s_w1[i] = w1[(i & 15) * 27 + (i >> 4)];
        for (int i = tid; i < 2304; i += 256) {
            int co = i & 15, r = i >> 4;
            s_w2[i] = w2[co * 144 + r];
            s_w3[i] = w3[co * 144 + r];
        }
    }
    __syncthreads();

    // ---- Stage B: conv1 (3 -> 16), out region 16 rows x 32 cols -> s_h1 ----
    // Intermediates outside the image must be EXACT zero (per-layer SAME
    // padding in the reference) -> mask on store.
    {
        ull acc[2][8];
#pragma unroll
        for (int p = 0; p < 2; ++p)
#pragma unroll
            for (int q = 0; q < 8; ++q) acc[p][q] = 0ULL;

        conv_block<3, 36, 648>(s_in, s_w1, 2 * tx, ty, acc);

        int gx = ox - 2 + 2 * tx;
        int gy = oy - 2 + ty;
        float rowm = ((unsigned)gy < IMG_H) ? 1.0f : 0.0f;
        ull mask = pk2(((unsigned)gx < IMG_W) ? rowm : 0.0f,
                       ((unsigned)(gx + 1) < IMG_W) ? rowm : 0.0f);
        float* hp = s_h1 + ty * 34 + 2 * tx;
#pragma unroll
        for (int q = 0; q < 8; ++q)
            mstore(hp + (2 * q) * 544, hp + (2 * q + 1) * 544,
                   acc[0][q], acc[1][q], mask);
    }
    __syncthreads();

    // ---- Stage C: conv2 (16 -> 16), out region 14 rows x 30 cols -> s_h2 ----
    if (ty < 14) {   // warp-uniform (warp = 2 consecutive ty)
        ull acc[2][8];
#pragma unroll
        for (int p = 0; p < 2; ++p)
#pragma unroll
            for (int q = 0; q < 8; ++q) acc[p][q] = 0ULL;

        conv_block<16, 34, 544>(s_h1, s_w2, 2 * tx, ty, acc);

        if (tx < 15) {
            int gx = ox - 1 + 2 * tx;
            int gy = oy - 1 + ty;
            float rowm = ((unsigned)gy < IMG_H) ? 1.0f : 0.0f;
            ull mask = pk2(((unsigned)gx < IMG_W) ? rowm : 0.0f,
                           ((unsigned)(gx + 1) < IMG_W) ? rowm : 0.0f);
            float* hp = s_h2 + ty * 32 + 2 * tx;
#pragma unroll
            for (int q = 0; q < 8; ++q)
                mstore(hp + (2 * q) * 448, hp + (2 * q + 1) * 448,
                       acc[0][q], acc[1][q], mask);
        }
    }
    __syncthreads();

    // ---- Stage D: conv3 (16 -> 16) + ReLU, out 12 rows x 28 cols -> global --
    if (ty < 12) {   // warp-uniform
        ull acc[2][8];
#pragma unroll
        for (int p = 0; p < 2; ++p)
#pragma unroll
            for (int q = 0; q < 8; ++q) acc[p][q] = 0ULL;

        conv_block<16, 32, 448>(s_h2, s_w3, 2 * tx, ty, acc);

        int gx = ox + 2 * tx;
        int gy = oy + ty;                    // always < IMG_H (128*12 = 1536)
        if (tx < 14 && gx < IMG_W) {         // gx even -> gx+1 also in bounds
            float* ob = out + ((size_t)(bz * 16) * IMG_H + gy) * IMG_W + gx;
#pragma unroll
            for (int q = 0; q < 8; ++q) {
                float l0, l1, r0, r1;
                unpk2(acc[0][q], l0, l1);
                unpk2(acc[1][q], r0, r1);
                float2 v0 = make_float2(fmaxf(l0, 0.0f), fmaxf(r0, 0.0f));
                float2 v1 = make_float2(fmaxf(l1, 0.0f), fmaxf(r1, 0.0f));
                *(float2*)(ob + (size_t)(2 * q) * IMG_H * IMG_W)     = v0;
                *(float2*)(ob + (size_t)(2 * q + 1) * IMG_H * IMG_W) = v1;
            }
        }
    }
}

extern "C" void kernel_launch(void* const* d_in, const int* in_sizes, int n_in,
                              void* d_out, int out_size) {
    const float* x  = (const float*)d_in[0];
    const float* w1 = (const float*)d_in[1];
    const float* w2 = (const float*)d_in[2];
    const float* w3 = (const float*)d_in[3];
    float* out = (float*)d_out;

    cudaFuncSetAttribute(net_fused_kernel,
                         cudaFuncAttributeMaxDynamicSharedMemorySize, SMEM_BYTES);

    dim3 grid(NTX, NTY, NB);
    net_fused_kernel<<<grid, 256, SMEM_BYTES>>>(x, w1, w2, w3, out);
}

// round 7
// speedup vs baseline: 1.6144x; 1.6144x over previous
#include <cuda_runtime.h>
#include <cstdint>

#define IMG_H 1536
#define IMG_W 1536
#define NB    4
#define TO    28          // output tile edge
#define NT    55          // ceil(1536/28)

typedef unsigned long long ull;

// ---------------- f32x2 packed helpers (sm_103a) ----------------
__device__ __forceinline__ ull pk2(float lo, float hi) {
    ull r;
    asm("mov.b64 %0, {%1, %2};" : "=l"(r) : "f"(lo), "f"(hi));
    return r;
}
__device__ __forceinline__ void ffma2(ull& d, ull a, ull b) {
    asm("fma.rn.f32x2 %0, %1, %2, %0;" : "+l"(d) : "l"(a), "l"(b));
}
__device__ __forceinline__ void unpk2(ull v, float& lo, float& hi) {
    asm("mov.b64 {%0, %1}, %2;" : "=f"(lo), "=f"(hi) : "l"(v));
}

// Conv inner block. Co-pair packed accumulators:
//   acc[k][p][q] = packed (co=2q, co=2q+1) partial sums for output pixel
//                  (row = k ? r1 : r0, col = col + p),  k,p in {0,1}, q in 0..7.
// Weights in smem in PLAIN layout sw[(cin*9+t)*16 + co] (co contiguous):
//   one LDS.128 (ulonglong2) -> 4 weights (2 co-pairs) -> feeds 8 FFMA2.
// Input pixels duplicated into both packed lanes with one mov.b64 (alu pipe).
template<int CIN, int ISTR, int IPLANE>
__device__ __forceinline__ void conv_block(const float* __restrict__ sin,
                                           const float* __restrict__ sw,
                                           int col, int r0, int r1,
                                           ull acc[2][2][8]) {
#pragma unroll 1
    for (int cin = 0; cin < CIN; ++cin) {
        const float* base = sin + cin * IPLANE + col;
        ull dup[2][3][4];
#pragma unroll
        for (int k = 0; k < 2; ++k) {
            int r = k ? r1 : r0;
#pragma unroll
            for (int dy = 0; dy < 3; ++dy) {
                const float* p = base + (r + dy) * ISTR;
                float2 a = *(const float2*)p;         // cols col, col+1
                float2 b = *(const float2*)(p + 2);   // cols col+2, col+3
                dup[k][dy][0] = pk2(a.x, a.x);
                dup[k][dy][1] = pk2(a.y, a.y);
                dup[k][dy][2] = pk2(b.x, b.x);
                dup[k][dy][3] = pk2(b.y, b.y);
            }
        }
        const ulonglong2* w = (const ulonglong2*)sw + cin * 36;
#pragma unroll
        for (int t = 0; t < 9; ++t) {
            const int dy = t / 3, kx = t % 3;
#pragma unroll
            for (int j = 0; j < 4; ++j) {
                ulonglong2 wv = w[t * 4 + j];     // co 4j..4j+3
#pragma unroll
                for (int k = 0; k < 2; ++k) {
                    ffma2(acc[k][0][2 * j],     dup[k][dy][kx],     wv.x);
                    ffma2(acc[k][1][2 * j],     dup[k][dy][kx + 1], wv.x);
                    ffma2(acc[k][0][2 * j + 1], dup[k][dy][kx],     wv.y);
                    ffma2(acc[k][1][2 * j + 1], dup[k][dy][kx + 1], wv.y);
                }
            }
        }
    }
}

// Transpose one (co-pair, 2-col) acc pair into 2 col-pair words, mask, store.
__device__ __forceinline__ void mstore(float* p0, float* p1, ull aL, ull aR, ull mask) {
    float l0, l1, r0, r1;
    unpk2(aL, l0, l1);              // col L: co 2q, 2q+1
    unpk2(aR, r0, r1);              // col R: co 2q, 2q+1
    ull v0 = pk2(l0, r0);           // plane 2q   : (colL, colR)
    ull v1 = pk2(l1, r1);           // plane 2q+1 : (colL, colR)
    asm("mul.rn.f32x2 %0, %0, %1;" : "+l"(v0) : "l"(mask));
    asm("mul.rn.f32x2 %0, %0, %1;" : "+l"(v1) : "l"(mask));
    *(ull*)p0 = v0;
    *(ull*)p1 = v1;
}

// smem layout (floats):
//  s_h1 : 16*32*34 = 17408   conv1 out (halo 2), row stride 34
//  s_h2 : 16*30*32 = 15360   conv2 out (halo 1), row stride 32
//  s_in : 3*34*36  = 3672    input tile (halo 3), row stride 36
//  s_w1 : 432   s_w2 : 2304   s_w3 : 2304   (plain layout, co innermost)
// total = 41480 floats = 165920 bytes -> 1 CTA/SM
#define SMEM_BYTES 165920

__global__ __launch_bounds__(256, 1)
void net_fused_kernel(const float* __restrict__ x,
                      const float* __restrict__ w1,
                      const float* __restrict__ w2,
                      const float* __restrict__ w3,
                      float* __restrict__ out) {
    extern __shared__ float sm[];
    float* s_h1 = sm;                 // 17408
    float* s_h2 = s_h1 + 17408;       // 15360
    float* s_in = s_h2 + 15360;       // 3672
    float* s_w1 = s_in + 3672;        // 432
    float* s_w2 = s_w1 + 432;         // 2304
    float* s_w3 = s_w2 + 2304;        // 2304

    const int tid = threadIdx.x;
    const int tx = tid & 15;          // col pair 2*tx
    const int ty = tid >> 4;          // rows ty, ty+16
    const int ox = blockIdx.x * TO;
    const int oy = blockIdx.y * TO;
    const int bz = blockIdx.z;

    // ---- Stage A: input halo tile (3 x 34 x 34, zero-padded) + weights ----
    {
        const float* xb = x + (size_t)bz * 3 * IMG_H * IMG_W;
        for (int i = tid; i < 3 * 34 * 34; i += 256) {
            int cin = i / 1156;
            int rem = i - cin * 1156;
            int rr  = rem / 34;
            int cc  = rem - rr * 34;
            int gy = oy - 3 + rr;
            int gx = ox - 3 + cc;
            float v = 0.0f;
            if ((unsigned)gy < IMG_H && (unsigned)gx < IMG_W)
                v = xb[(size_t)cin * IMG_H * IMG_W + (size_t)gy * IMG_W + gx];
            s_in[cin * 1224 + rr * 36 + cc] = v;
        }
        // transpose weights: s_w[(cin*9+t)*16 + co] = w[co][cin*9+t]
        for (int i = tid; i < 432; i += 256)
            s_w1[i] = w1[(i & 15) * 27 + (i >> 4)];
        for (int i = tid; i < 2304; i += 256) {
            int co = i & 15, r = i >> 4;
            s_w2[i] = w2[co * 144 + r];
            s_w3[i] = w3[co * 144 + r];
        }
    }
    __syncthreads();

    // ---- Stage B: conv1 (3 -> 16) over 32x32 region -> s_h1 ----
    // Intermediates outside the image must be EXACT zero (the reference
    // zero-pads every conv layer) -> mask on store.
    {
        ull acc[2][2][8];
#pragma unroll
        for (int k = 0; k < 2; ++k)
#pragma unroll
            for (int p = 0; p < 2; ++p)
#pragma unroll
                for (int q = 0; q < 8; ++q) acc[k][p][q] = 0ULL;

        conv_block<3, 36, 1224>(s_in, s_w1, 2 * tx, ty, ty + 16, acc);

        int gx = ox - 2 + 2 * tx;
#pragma unroll
        for (int k = 0; k < 2; ++k) {
            int r = k ? (ty + 16) : ty;
            int gy = oy - 2 + r;
            float rowm = ((unsigned)gy < IMG_H) ? 1.0f : 0.0f;
            ull mask = pk2(((unsigned)gx < IMG_W) ? rowm : 0.0f,
                           ((unsigned)(gx + 1) < IMG_W) ? rowm : 0.0f);
            float* hp = s_h1 + r * 34 + 2 * tx;
#pragma unroll
            for (int q = 0; q < 8; ++q)
                mstore(hp + (2 * q) * 1088, hp + (2 * q + 1) * 1088,
                       acc[k][0][q], acc[k][1][q], mask);
        }
    }
    __syncthreads();

    // ---- Stage C: conv2 (16 -> 16) over 30x30 region -> s_h2 ----
    {
        ull acc[2][2][8];
#pragma unroll
        for (int k = 0; k < 2; ++k)
#pragma unroll
            for (int p = 0; p < 2; ++p)
#pragma unroll
                for (int q = 0; q < 8; ++q) acc[k][p][q] = 0ULL;

        int r1 = (ty < 14) ? (ty + 16) : 0;   // clamp loads for inactive row
        conv_block<16, 34, 1088>(s_h1, s_w2, 2 * tx, ty, r1, acc);

        if (tx < 15) {
            int gx = ox - 1 + 2 * tx;
#pragma unroll
            for (int k = 0; k < 2; ++k) {
                if (k && ty >= 14) break;
                int r = k ? (ty + 16) : ty;
                int gy = oy - 1 + r;
                float rowm = ((unsigned)gy < IMG_H) ? 1.0f : 0.0f;
                ull mask = pk2(((unsigned)gx < IMG_W) ? rowm : 0.0f,
                               ((unsigned)(gx + 1) < IMG_W) ? rowm : 0.0f);
                float* hp = s_h2 + r * 32 + 2 * tx;
#pragma unroll
                for (int q = 0; q < 8; ++q)
                    mstore(hp + (2 * q) * 960, hp + (2 * q + 1) * 960,
                           acc[k][0][q], acc[k][1][q], mask);
            }
        }
    }
    __syncthreads();

    // ---- Stage D: conv3 (16 -> 16) + ReLU over 28x28 -> global ----
    {
        ull acc[2][2][8];
#pragma unroll
        for (int k = 0; k < 2; ++k)
#pragma unroll
            for (int p = 0; p < 2; ++p)
#pragma unroll
                for (int q = 0; q < 8; ++q) acc[k][p][q] = 0ULL;

        int r1 = (ty < 12) ? (ty + 16) : 0;
        conv_block<16, 32, 960>(s_h2, s_w3, 2 * tx, ty, r1, acc);

        if (tx < 14) {
            int gx = ox + 2 * tx;
#pragma unroll
            for (int k = 0; k < 2; ++k) {
                if (k && ty >= 12) break;
                int r = k ? (ty + 16) : ty;
                int gy = oy + r;
                if (gy >= IMG_H || gx >= IMG_W) continue;   // gx even -> gx+1 ok
                float* ob = out + ((size_t)(bz * 16) * IMG_H + gy) * IMG_W + gx;
#pragma unroll
                for (int q = 0; q < 8; ++q) {
                    float l0, l1, r0, r1v;
                    unpk2(acc[k][0][q], l0, l1);
                    unpk2(acc[k][1][q], r0, r1v);
                    float2 v0 = make_float2(fmaxf(l0, 0.0f), fmaxf(r0, 0.0f));
                    float2 v1 = make_float2(fmaxf(l1, 0.0f), fmaxf(r1v, 0.0f));
                    *(float2*)(ob + (size_t)(2 * q) * IMG_H * IMG_W)     = v0;
                    *(float2*)(ob + (size_t)(2 * q + 1) * IMG_H * IMG_W) = v1;
                }
            }
        }
    }
}

extern "C" void kernel_launch(void* const* d_in, const int* in_sizes, int n_in,
                              void* d_out, int out_size) {
    const float* x  = (const float*)d_in[0];
    const float* w1 = (const float*)d_in[1];
    const float* w2 = (const float*)d_in[2];
    const float* w3 = (const float*)d_in[3];
    float* out = (float*)d_out;

    cudaFuncSetAttribute(net_fused_kernel,
                         cudaFuncAttributeMaxDynamicSharedMemorySize, SMEM_BYTES);

    dim3 grid(NT, NT, NB);
    net_fused_kernel<<<grid, 256, SMEM_BYTES>>>(x, w1, w2, w3, out);
}